// round 1
// baseline (speedup 1.0000x reference)
#include <cuda_runtime.h>

// ---------------- problem constants ----------------
#define DB 2
#define DS 2048
#define DD 512
#define DM 64
#define DT 2112              // DM + DS
#define DN 4224              // DB * DT
#define DH 8
#define DHD 64
#define DWIN 512
#define NSPLIT 8
#define SPLITROWS 528        // DN / NSPLIT
#define NLAY 2
#define LRC 1e-3f
#define WDC 1e-2f
#define EPSC 1e-8f
#define MAXALR 0.01f

// ---------------- scratch (device globals; no allocs allowed) ----------------
static __device__ float g_XM[DN * DD];
static __device__ float g_K[DN * DD];
static __device__ float g_V[DN * DD];
static __device__ float g_Q[DN * DD];
static __device__ float g_LR[DN];
static __device__ float g_Z0[DN * DD];
static __device__ float g_X1[DN * DD];
static __device__ float g_Z1[DN * DD];
static __device__ float g_X2[DN * DD];
static __device__ float g_DY2[DN * DD];
static __device__ float g_DZ1[DN * DD];
static __device__ float g_DX1[DN * DD];
static __device__ float g_DZ0[DN * DD];
static __device__ float g_Wn[NLAY * DD * DD];
static __device__ float g_Y1[DN * DD];
static __device__ float g_Y2[DN * DD];
static __device__ float g_AQ[DN * DD];
static __device__ float g_AK[DN * DD];
static __device__ float g_AV[DN * DD];
static __device__ float g_AO[DN * DD];
static __device__ float g_S[DB * DH * DT * DWIN];               // banded scores/probs
static __device__ float g_GP[NLAY * NSPLIT * DD * DD];          // split-K grad partials

__device__ __forceinline__ float sigf(float z) { return 1.0f / (1.0f + __expf(-z)); }
__device__ __forceinline__ float silup(float z) {
    float s = sigf(z);
    return s * (1.0f + z * (1.0f - s));
}

#define FMA4x4(a, bb) do { \
    acc[0][0] = fmaf(a.x, bb.x, acc[0][0]); acc[0][1] = fmaf(a.x, bb.y, acc[0][1]); \
    acc[0][2] = fmaf(a.x, bb.z, acc[0][2]); acc[0][3] = fmaf(a.x, bb.w, acc[0][3]); \
    acc[1][0] = fmaf(a.y, bb.x, acc[1][0]); acc[1][1] = fmaf(a.y, bb.y, acc[1][1]); \
    acc[1][2] = fmaf(a.y, bb.z, acc[1][2]); acc[1][3] = fmaf(a.y, bb.w, acc[1][3]); \
    acc[2][0] = fmaf(a.z, bb.x, acc[2][0]); acc[2][1] = fmaf(a.z, bb.y, acc[2][1]); \
    acc[2][2] = fmaf(a.z, bb.z, acc[2][2]); acc[2][3] = fmaf(a.z, bb.w, acc[2][3]); \
    acc[3][0] = fmaf(a.w, bb.x, acc[3][0]); acc[3][1] = fmaf(a.w, bb.y, acc[3][1]); \
    acc[3][2] = fmaf(a.w, bb.z, acc[3][2]); acc[3][3] = fmaf(a.w, bb.w, acc[3][3]); \
} while (0)

// ---------------- build xm = concat(meta, x) ----------------
__global__ void build_xm_k(const float* __restrict__ x, const float* __restrict__ meta,
                           float* __restrict__ XM) {
    int idx = blockIdx.x * blockDim.x + threadIdx.x;   // float4 index
    if (idx >= DN * DD / 4) return;
    int e = idx << 2;
    int n = e / DD, d = e - n * DD;
    int b = n / DT, t = n - b * DT;
    float4 v;
    if (t < DM) v = *(const float4*)&meta[t * DD + d];
    else        v = *(const float4*)&x[(b * DS + (t - DM)) * DD + d];
    *(float4*)&XM[e] = v;
}

// ---------------- adaptive lr: sigmoid(xm @ w_lr^T) * MAXALR ----------------
__global__ void lr_proj_k(const float* __restrict__ XM, const float* __restrict__ wlr,
                          float* __restrict__ out) {
    int warp = (blockIdx.x * blockDim.x + threadIdx.x) >> 5;
    int lane = threadIdx.x & 31;
    if (warp >= DN) return;
    const float* xr = XM + warp * DD;
    float s = 0.0f;
#pragma unroll
    for (int i = 0; i < DD / 32; i++) s = fmaf(xr[lane + i * 32], wlr[lane + i * 32], s);
#pragma unroll
    for (int o = 16; o > 0; o >>= 1) s += __shfl_xor_sync(0xffffffffu, s, o);
    if (lane == 0) out[warp] = MAXALR * sigf(s);
}

// ---------------- GEMM NT:  C = A @ W^T  (A [R,512], W [512,512]) ----------------
// EPI 0: store acc to Cz
// EPI 1: Cz = acc ; Cx = A + silu(acc)      (residual MLP layer fwd)
// EPI 2: Cx(d_out) = acc, mapped rows t>=DM only
template <int EPI>
__global__ void __launch_bounds__(256, 4) gemm_nt_k(
    const float* __restrict__ A, const float* __restrict__ W,
    float* __restrict__ Cz, float* __restrict__ Cx) {
    __shared__ float As[16][68];
    __shared__ float Bs[16][68];
    const int tid = threadIdx.x;
    const int tx = tid & 15, ty = tid >> 4;
    const int m0 = blockIdx.x << 6, n0 = blockIdx.y << 6;
    const int lr = tid >> 2;
    const int lc = (tid & 3) << 2;
    const float* Ap = A + (m0 + lr) * DD + lc;
    const float* Wp = W + (n0 + lr) * DD + lc;
    float acc[4][4] = {};
    for (int k0 = 0; k0 < DD; k0 += 16) {
        float4 av = *(const float4*)(Ap + k0);
        float4 wv = *(const float4*)(Wp + k0);
        As[lc + 0][lr] = av.x; As[lc + 1][lr] = av.y; As[lc + 2][lr] = av.z; As[lc + 3][lr] = av.w;
        Bs[lc + 0][lr] = wv.x; Bs[lc + 1][lr] = wv.y; Bs[lc + 2][lr] = wv.z; Bs[lc + 3][lr] = wv.w;
        __syncthreads();
#pragma unroll
        for (int kk = 0; kk < 16; kk++) {
            float4 a = *(const float4*)&As[kk][tx << 2];
            float4 b = *(const float4*)&Bs[kk][ty << 2];
            FMA4x4(a, b);
        }
        __syncthreads();
    }
    const int m = m0 + (tx << 2);
    const int n = n0 + (ty << 2);
#pragma unroll
    for (int i = 0; i < 4; i++) {
#pragma unroll
        for (int j = 0; j < 4; j++) {
            int row = m + i, col = n + j;
            float z = acc[i][j];
            if (EPI == 0) {
                Cz[row * DD + col] = z;
            } else if (EPI == 1) {
                Cz[row * DD + col] = z;
                Cx[row * DD + col] = A[row * DD + col] + z * sigf(z);
            } else {
                int bb = row / DT, t = row - bb * DT;
                if (t >= DM) Cx[(bb * DS + (t - DM)) * DD + col] = z;
            }
        }
    }
}

// ---------------- GEMM NN + residual:  C = R + A @ W ----------------
__global__ void __launch_bounds__(256, 4) gemm_nn_res_k(
    const float* __restrict__ A, const float* __restrict__ W,
    const float* __restrict__ R, float* __restrict__ C) {
    __shared__ float As[16][68];   // As[k][m]
    __shared__ float Bs[16][68];   // Bs[k][n]
    const int tid = threadIdx.x;
    const int tx = tid & 15, ty = tid >> 4;
    const int m0 = blockIdx.x << 6, n0 = blockIdx.y << 6;
    const int lr = tid >> 2;
    const int lc = (tid & 3) << 2;
    const int r16 = tid >> 4;            // 0..15 (k row for B tile)
    const int c64 = (tid & 15) << 2;     // 0..60 (n col for B tile)
    const float* Ap = A + (m0 + lr) * DD + lc;
    float acc[4][4] = {};
    for (int k0 = 0; k0 < DD; k0 += 16) {
        float4 av = *(const float4*)(Ap + k0);
        As[lc + 0][lr] = av.x; As[lc + 1][lr] = av.y; As[lc + 2][lr] = av.z; As[lc + 3][lr] = av.w;
        *(float4*)&Bs[r16][c64] = *(const float4*)&W[(k0 + r16) * DD + n0 + c64];
        __syncthreads();
#pragma unroll
        for (int kk = 0; kk < 16; kk++) {
            float4 a = *(const float4*)&As[kk][tx << 2];
            float4 b = *(const float4*)&Bs[kk][ty << 2];
            FMA4x4(a, b);
        }
        __syncthreads();
    }
    const int m = m0 + (tx << 2);
    const int n = n0 + (ty << 2);
#pragma unroll
    for (int i = 0; i < 4; i++)
#pragma unroll
        for (int j = 0; j < 4; j++) {
            int row = m + i, col = n + j;
            C[row * DD + col] = acc[i][j] + R[row * DD + col];
        }
}

// ---------------- GEMM TN split-K:  Gp[split] = Dz^T @ X over its row slice ----------------
__global__ void __launch_bounds__(256, 4) gemm_tn_k(
    const float* __restrict__ Dz, const float* __restrict__ Xv, float* __restrict__ Gp) {
    __shared__ float As[16][68];   // As[n][i]
    __shared__ float Bs[16][68];   // Bs[n][j]
    const int tid = threadIdx.x;
    const int tx = tid & 15, ty = tid >> 4;
    const int i0 = blockIdx.x << 6, j0 = blockIdx.y << 6;
    const int sp = blockIdx.z;
    const int base = sp * SPLITROWS;
    const int r16 = tid >> 4;
    const int c64 = (tid & 15) << 2;
    float acc[4][4] = {};
    for (int n0 = base; n0 < base + SPLITROWS; n0 += 16) {
        *(float4*)&As[r16][c64] = *(const float4*)&Dz[(n0 + r16) * DD + i0 + c64];
        *(float4*)&Bs[r16][c64] = *(const float4*)&Xv[(n0 + r16) * DD + j0 + c64];
        __syncthreads();
#pragma unroll
        for (int kk = 0; kk < 16; kk++) {
            float4 a = *(const float4*)&As[kk][tx << 2];
            float4 b = *(const float4*)&Bs[kk][ty << 2];
            FMA4x4(a, b);
        }
        __syncthreads();
    }
    float* out = Gp + sp * DD * DD;
    const int ii = i0 + (tx << 2);
    const int jj = j0 + (ty << 2);
#pragma unroll
    for (int i = 0; i < 4; i++)
#pragma unroll
        for (int j = 0; j < 4; j++)
            out[(ii + i) * DD + jj + j] = acc[i][j];
}

// ---------------- head gradient + layer1 activation backward (fused) ----------------
__global__ void grad_head_k(const float* __restrict__ X2, const float* __restrict__ Vv,
                            const float* __restrict__ Z1, const float* __restrict__ LRv,
                            float* __restrict__ DY2, float* __restrict__ DZ1) {
    int i = blockIdx.x * blockDim.x + threadIdx.x;
    if (i >= DN * DD) return;
    int n = i >> 9;
    float c = (2.0f / (float)DD) * LRv[n];
    float d2 = c * (X2[i] - Vv[i]);
    DY2[i] = d2;
    DZ1[i] = d2 * silup(Z1[i]);
}

__global__ void bwd_act0_k(const float* __restrict__ DX1, const float* __restrict__ Z0,
                           float* __restrict__ DZ0) {
    int i = blockIdx.x * blockDim.x + threadIdx.x;
    if (i >= DN * DD) return;
    DZ0[i] = DX1[i] * silup(Z0[i]);
}

// ---------------- reduce split-K partials + AdamW first step ----------------
__global__ void adamw_k(const float* __restrict__ W, float* __restrict__ Wn) {
    int idx = blockIdx.x * blockDim.x + threadIdx.x;
    if (idx >= NLAY * DD * DD) return;
    int l = idx / (DD * DD);
    int e = idx - l * (DD * DD);
    const float* gp = g_GP + l * NSPLIT * DD * DD;
    float g = 0.0f;
#pragma unroll
    for (int s = 0; s < NSPLIT; s++) g += gp[s * DD * DD + e];
    g *= (1.0f / 16.0f);
    float w = W[idx];
    Wn[idx] = w * (1.0f - LRC * WDC) - LRC * g / (fabsf(g) + EPSC);
}

// ---------------- attention: banded scores ----------------
__global__ void __launch_bounds__(256, 2) attn_scores_k(
    const float* __restrict__ AQ, const float* __restrict__ AK, float* __restrict__ Sb) {
    __shared__ float Qs[64][68];   // Qs[c][q]
    __shared__ float Ks[64][68];   // Ks[c][k]
    const int q0 = blockIdx.x << 6;
    const int h = blockIdx.y, b = blockIdx.z;
    const int tid = threadIdx.x;
    const int tx = tid & 15, ty = tid >> 4;
#pragma unroll
    for (int i = 0; i < 4; i++) {
        int idx = tid + (i << 8);                 // float4 index 0..1023
        int r = idx >> 4, c4 = (idx & 15) << 2;
        float4 v = *(const float4*)&AQ[(b * DT + q0 + r) * DD + h * DHD + c4];
        Qs[c4 + 0][r] = v.x; Qs[c4 + 1][r] = v.y; Qs[c4 + 2][r] = v.z; Qs[c4 + 3][r] = v.w;
    }
    __syncthreads();
    int kLo = q0 - (DWIN - 1);
    if (kLo < 0) kLo = 0;
    kLo &= ~63;
    for (int k0 = kLo; k0 <= q0 + 63; k0 += 64) {
#pragma unroll
        for (int i = 0; i < 4; i++) {
            int idx = tid + (i << 8);
            int r = idx >> 4, c4 = (idx & 15) << 2;
            int k = k0 + r;
            float4 v = make_float4(0.f, 0.f, 0.f, 0.f);
            if (k < DT) v = *(const float4*)&AK[(b * DT + k) * DD + h * DHD + c4];
            Ks[c4 + 0][r] = v.x; Ks[c4 + 1][r] = v.y; Ks[c4 + 2][r] = v.z; Ks[c4 + 3][r] = v.w;
        }
        __syncthreads();
        float acc[4][4] = {};
#pragma unroll 16
        for (int cc = 0; cc < 64; cc++) {
            float4 a = *(const float4*)&Qs[cc][tx << 2];
            float4 bb = *(const float4*)&Ks[cc][ty << 2];
            FMA4x4(a, bb);
        }
#pragma unroll
        for (int i = 0; i < 4; i++)
#pragma unroll
            for (int j = 0; j < 4; j++) {
                int q = q0 + (tx << 2) + i;
                int k = k0 + (ty << 2) + j;
                if (k <= q && q - k < DWIN)
                    Sb[((b * DH + h) * DT + q) * DWIN + (k - q + DWIN - 1)] = acc[i][j] * 0.125f;
            }
        __syncthreads();
    }
}

// ---------------- attention: softmax over band (warp per row) ----------------
__global__ void attn_softmax_k(float* __restrict__ Sb) {
    int gw = (blockIdx.x * blockDim.x + threadIdx.x) >> 5;
    int lane = threadIdx.x & 31;
    if (gw >= DB * DH * DT) return;
    int q = gw % DT;
    int wlo = DWIN - 1 - q;
    if (wlo < 0) wlo = 0;
    float* row = Sb + gw * DWIN;
    float v[16];
    float m = -1e30f;
#pragma unroll
    for (int i = 0; i < 16; i++) {
        int w = lane + i * 32;
        v[i] = (w >= wlo) ? row[w] : -1e30f;
        m = fmaxf(m, v[i]);
    }
#pragma unroll
    for (int o = 16; o > 0; o >>= 1) m = fmaxf(m, __shfl_xor_sync(0xffffffffu, m, o));
    float sum = 0.0f;
#pragma unroll
    for (int i = 0; i < 16; i++) {
        int w = lane + i * 32;
        v[i] = (w >= wlo) ? __expf(v[i] - m) : 0.0f;
        sum += v[i];
    }
#pragma unroll
    for (int o = 16; o > 0; o >>= 1) sum += __shfl_xor_sync(0xffffffffu, sum, o);
    float inv = 1.0f / sum;
#pragma unroll
    for (int i = 0; i < 16; i++) {
        int w = lane + i * 32;
        if (w >= wlo) row[w] = v[i] * inv;
    }
}

// ---------------- attention: P @ V ----------------
__global__ void __launch_bounds__(256, 2) attn_pv_k(
    const float* __restrict__ Sb, const float* __restrict__ AV, float* __restrict__ AO) {
    __shared__ float Ps[64][68];   // Ps[k][q]
    __shared__ float Vs[64][68];   // Vs[k][c]
    const int q0 = blockIdx.x << 6;
    const int h = blockIdx.y, b = blockIdx.z;
    const int tid = threadIdx.x;
    const int tx = tid & 15, ty = tid >> 4;
    float acc[4][4] = {};
    int kLo = q0 - (DWIN - 1);
    if (kLo < 0) kLo = 0;
    kLo &= ~63;
    for (int k0 = kLo; k0 <= q0 + 63; k0 += 64) {
#pragma unroll
        for (int i = 0; i < 4; i++) {
            int idx = tid + (i << 8);
            int r = idx >> 4, c4 = (idx & 15) << 2;
            int k = k0 + r;
            float4 v = make_float4(0.f, 0.f, 0.f, 0.f);
            if (k < DT) v = *(const float4*)&AV[(b * DT + k) * DD + h * DHD + c4];
            *(float4*)&Vs[r][c4] = v;
        }
#pragma unroll
        for (int i = 0; i < 16; i++) {
            int lin = tid + (i << 8);              // 0..4095
            int qi = lin >> 6, kj = lin & 63;
            int q = q0 + qi, k = k0 + kj;
            float p = 0.0f;
            if (k <= q && q - k < DWIN)
                p = Sb[((b * DH + h) * DT + q) * DWIN + (k - q + DWIN - 1)];
            Ps[kj][qi] = p;
        }
        __syncthreads();
#pragma unroll 16
        for (int kk = 0; kk < 64; kk++) {
            float4 a = *(const float4*)&Ps[kk][tx << 2];
            float4 bb = *(const float4*)&Vs[kk][ty << 2];
            FMA4x4(a, bb);
        }
        __syncthreads();
    }
#pragma unroll
    for (int i = 0; i < 4; i++)
#pragma unroll
        for (int j = 0; j < 4; j++)
            AO[(b * DT + q0 + (tx << 2) + i) * DD + h * DHD + (ty << 2) + j] = acc[i][j];
}

// ---------------- host ----------------
extern "C" void kernel_launch(void* const* d_in, const int* in_sizes, int n_in,
                              void* d_out, int out_size) {
    const float* x      = (const float*)d_in[0];
    const float* meta   = (const float*)d_in[1];
    const float* lmm_w  = (const float*)d_in[2];
    const float* w_q    = (const float*)d_in[3];
    const float* w_k    = (const float*)d_in[4];
    const float* w_v    = (const float*)d_in[5];
    const float* w_lr   = (const float*)d_in[6];
    const float* swa_wq = (const float*)d_in[7];
    const float* swa_wk = (const float*)d_in[8];
    const float* swa_wv = (const float*)d_in[9];
    const float* swa_wo = (const float*)d_in[10];
    float* out = (float*)d_out;

    float *XM, *K, *V, *Q, *LR, *Z0, *X1, *Z1, *X2, *DY2, *DZ1, *DX1, *DZ0;
    float *Wn, *Y1, *Y2, *AQ, *AK, *AV, *AO, *Sb, *GP;
    cudaGetSymbolAddress((void**)&XM, g_XM);
    cudaGetSymbolAddress((void**)&K, g_K);
    cudaGetSymbolAddress((void**)&V, g_V);
    cudaGetSymbolAddress((void**)&Q, g_Q);
    cudaGetSymbolAddress((void**)&LR, g_LR);
    cudaGetSymbolAddress((void**)&Z0, g_Z0);
    cudaGetSymbolAddress((void**)&X1, g_X1);
    cudaGetSymbolAddress((void**)&Z1, g_Z1);
    cudaGetSymbolAddress((void**)&X2, g_X2);
    cudaGetSymbolAddress((void**)&DY2, g_DY2);
    cudaGetSymbolAddress((void**)&DZ1, g_DZ1);
    cudaGetSymbolAddress((void**)&DX1, g_DX1);
    cudaGetSymbolAddress((void**)&DZ0, g_DZ0);
    cudaGetSymbolAddress((void**)&Wn, g_Wn);
    cudaGetSymbolAddress((void**)&Y1, g_Y1);
    cudaGetSymbolAddress((void**)&Y2, g_Y2);
    cudaGetSymbolAddress((void**)&AQ, g_AQ);
    cudaGetSymbolAddress((void**)&AK, g_AK);
    cudaGetSymbolAddress((void**)&AV, g_AV);
    cudaGetSymbolAddress((void**)&AO, g_AO);
    cudaGetSymbolAddress((void**)&Sb, g_S);
    cudaGetSymbolAddress((void**)&GP, g_GP);

    const dim3 gN(DN / 64, DD / 64);         // 66 x 8
    const dim3 gTN(DD / 64, DD / 64, NSPLIT); // 8 x 8 x 8
    const dim3 gAT(DT / 64, DH, DB);          // 33 x 8 x 2
    const int EW = (DN * DD + 255) / 256;

    // 1. concat meta + x
    build_xm_k<<<(DN * DD / 4 + 255) / 256, 256>>>(x, meta, XM);
    // 2. projections
    gemm_nt_k<0><<<gN, 256>>>(XM, w_k, K, nullptr);
    gemm_nt_k<0><<<gN, 256>>>(XM, w_v, V, nullptr);
    gemm_nt_k<0><<<gN, 256>>>(XM, w_q, Q, nullptr);
    lr_proj_k<<<(DN * 32 + 255) / 256, 256>>>(XM, w_lr, LR);
    // 3. LMM forward on keys (save z for backward)
    gemm_nt_k<1><<<gN, 256>>>(K, lmm_w, Z0, X1);
    gemm_nt_k<1><<<gN, 256>>>(X1, lmm_w + DD * DD, Z1, X2);
    // 4. backward
    grad_head_k<<<EW, 256>>>(X2, V, Z1, LR, DY2, DZ1);
    gemm_tn_k<<<gTN, 256>>>(DZ1, X1, GP + 1 * NSPLIT * DD * DD);   // dW1 partials
    gemm_nn_res_k<<<gN, 256>>>(DZ1, lmm_w + DD * DD, DY2, DX1);    // dx1
    bwd_act0_k<<<EW, 256>>>(DX1, Z0, DZ0);
    gemm_tn_k<<<gTN, 256>>>(DZ0, K, GP);                           // dW0 partials
    // 5. AdamW first step
    adamw_k<<<(NLAY * DD * DD + 255) / 256, 256>>>(lmm_w, Wn);
    // 6. retrieval with updated weights (Z0/Z1 reused as scratch)
    gemm_nt_k<1><<<gN, 256>>>(Q, Wn, Z0, Y1);
    gemm_nt_k<1><<<gN, 256>>>(Y1, Wn + DD * DD, Z1, Y2);
    // 7. sliding-window attention
    gemm_nt_k<0><<<gN, 256>>>(Y2, swa_wq, AQ, nullptr);
    gemm_nt_k<0><<<gN, 256>>>(Y2, swa_wk, AK, nullptr);
    gemm_nt_k<0><<<gN, 256>>>(Y2, swa_wv, AV, nullptr);
    attn_scores_k<<<gAT, 256>>>(AQ, AK, Sb);
    attn_softmax_k<<<(DB * DH * DT * 32 + 255) / 256, 256>>>(Sb);
    attn_pv_k<<<gAT, 256>>>(Sb, AV, AO);
    // 8. output projection, dropping meta rows
    gemm_nt_k<2><<<gN, 256>>>(AO, swa_wo, nullptr, out);
}